// round 12
// baseline (speedup 1.0000x reference)
#include <cuda_runtime.h>
#include <cuda_bf16.h>
#include <cstdint>

#define NN 100000
#define EE 1600000
#define F0 256
#define FH 128
#define FC 40

// ---------------- static device scratch ----------------
__device__ float g_h[(size_t)NN * FH];    // layer-1 gemm output
__device__ float g_h2[(size_t)NN * FH];   // layer-2 gemm output
__device__ int   g_deg[NN];
__device__ float g_dinv[NN];
__device__ int   g_rowptr[NN + 1];
__device__ int   g_col[EE];
__device__ int   g_slot[EE];
__device__ float g_w[EE];
__device__ int   g_is64;
__device__ __nv_bfloat16 g_W1thi[FH * F0], g_W1tlo[FH * F0];   // [128][256] K-major
__device__ __nv_bfloat16 g_W2thi[FH * FH], g_W2tlo[FH * FH];   // [128][128] K-major
__device__ __nv_bfloat16 g_Wcthi[64 * FH], g_Wctlo[64 * FH];   // [64(pad40)][128] K-major

// ---------------- helpers ----------------
__device__ __forceinline__ uint32_t smem_u32(const void* p) {
    uint32_t a;
    asm("{ .reg .u64 t; cvta.to.shared.u64 t, %1; cvt.u32.u64 %0, t; }" : "=r"(a) : "l"(p));
    return a;
}
#define LDSM_X4(r0, r1, r2, r3, addr) \
    asm volatile("ldmatrix.sync.aligned.m8n8.x4.shared.b16 {%0,%1,%2,%3}, [%4];" \
                 : "=r"(r0), "=r"(r1), "=r"(r2), "=r"(r3) : "r"(addr))
#define MMA16816(d, a, b) \
    asm volatile("mma.sync.aligned.m16n8k16.row.col.f32.bf16.bf16.f32 " \
                 "{%0,%1,%2,%3}, {%4,%5,%6,%7}, {%8,%9}, {%0,%1,%2,%3};" \
                 : "+f"((d)[0]), "+f"((d)[1]), "+f"((d)[2]), "+f"((d)[3]) \
                 : "r"((a)[0]), "r"((a)[1]), "r"((a)[2]), "r"((a)[3]), \
                   "r"((b)[0]), "r"((b)[1]))
#define CP_ASYNC16(dst, src, sz) \
    asm volatile("cp.async.cg.shared.global [%0], [%1], 16, %2;" \
                 :: "r"(dst), "l"(src), "r"(sz) : "memory")
#define CP_COMMIT asm volatile("cp.async.commit_group;" ::: "memory")
#define CP_WAIT(n) asm volatile("cp.async.wait_group %0;" :: "n"(n) : "memory")

__device__ __forceinline__ int load_edge(const void* ei, long long idx, int is64) {
    if (is64) return (int)((const long long*)ei)[idx];
    return ((const int*)ei)[idx];
}
__device__ __forceinline__ void split1(float f, __nv_bfloat16& hi, __nv_bfloat16& lo) {
    hi = __float2bfloat16(f);
    lo = __float2bfloat16(f - __bfloat162float(hi));
}

#define SKEW 40
#define TILE_B (128 * SKEW * 2)     // 10240 bytes
#define STAGE_B (4 * TILE_B)
#define GSM_TOTAL (2 * STAGE_B)     // 81920 (gemm1)

// fused agg+gemm smem: A = 4 chunks hi (0..4*TILE) + 4 chunks lo (4*TILE..8*TILE)
// then single-buffered B (hi, lo)
#define FUSED_BBASE (8 * TILE_B)                    // 81920
#define F2_SM_TOTAL (FUSED_BBASE + 2 * TILE_B)      // 102400 (gemm2: B 128 rows)
#define BCT (64 * SKEW * 2)                          // 5120 (clf B tile, 64 rows)
#define FC_SM_TOTAL (FUSED_BBASE + 2 * BCT)          // 92160

// ================= K0: detect dtype + zero deg ===============================
__global__ void k0_detect_zero(const int* __restrict__ ei32, int total_words, int n) {
    if (blockIdx.x == 0) {
        __shared__ int acc;
        if (threadIdx.x == 0) acc = 0;
        __syncthreads();
        int v = 0;
        int lim = min(total_words, 8192);
        for (int i = 1 + 2 * threadIdx.x; i < lim; i += 2 * blockDim.x) v |= ei32[i];
        if (v) atomicOr(&acc, 1);
        __syncthreads();
        if (threadIdx.x == 0) g_is64 = (acc == 0) ? 1 : 0;
    } else {
        int i = (blockIdx.x - 1) * blockDim.x + threadIdx.x;
        if (i < n) g_deg[i] = 0;
    }
}

// ====== K1: deg+slot ∥ split_wt1 ∥ split_wt2 ∥ split_wc ======================
__global__ void k1_prep(const void* __restrict__ ei, int E,
                        const float* __restrict__ W1, const float* __restrict__ W2,
                        const float* __restrict__ Wc,
                        int bDeg, int bW1, int bW2) {
    int b = blockIdx.x, tid = threadIdx.x;
    if (b < bDeg) {
        int is64 = g_is64;
        int base = (b * 256 + tid) * 4;
        #pragma unroll
        for (int j = 0; j < 4; j++) {
            int i = base + j;
            if (i < E) {
                int d = load_edge(ei, (long long)E + i, is64);
                if ((unsigned)d < (unsigned)NN)
                    g_slot[i] = atomicAdd(&g_deg[d], 1);
            }
        }
    } else if (b < bDeg + bW1) {
        int i = (b - bDeg) * 256 + tid;
        if (i < F0 * FH) {
            int k = i / FH, nidx = i % FH;
            __nv_bfloat16 hi, lo;
            split1(W1[i], hi, lo);
            g_W1thi[nidx * F0 + k] = hi;
            g_W1tlo[nidx * F0 + k] = lo;
        }
    } else if (b < bDeg + bW1 + bW2) {
        int i = (b - bDeg - bW1) * 256 + tid;
        if (i < FH * FH) {
            int k = i / FH, nidx = i % FH;
            __nv_bfloat16 hi, lo;
            split1(W2[i], hi, lo);
            g_W2thi[nidx * FH + k] = hi;
            g_W2tlo[nidx * FH + k] = lo;
        }
    } else {
        int i = (b - bDeg - bW1 - bW2) * 256 + tid;
        if (i < 64 * FH) {
            int nidx = i / FH, k = i % FH;
            float f = (nidx < FC) ? Wc[k * FC + nidx] : 0.f;
            __nv_bfloat16 hi, lo;
            split1(f, hi, lo);
            g_Wcthi[nidx * FH + k] = hi;
            g_Wctlo[nidx * FH + k] = lo;
        }
    }
}

// ====== K1b: exclusive scan (block 0) ∥ dinv =================================
__global__ void k1b_scan_dinv(int n) {
    if (blockIdx.x == 0) {
        __shared__ int sh[256];
        int tid = threadIdx.x;
        int chunk = (n + 255) >> 8;
        int start = tid * chunk, end = min(start + chunk, n);
        int sum = 0;
        for (int i = start; i < end; i++) sum += g_deg[i];
        sh[tid] = sum;
        __syncthreads();
        for (int off = 1; off < 256; off <<= 1) {
            int v = 0;
            if (tid >= off) v = sh[tid - off];
            __syncthreads();
            sh[tid] += v;
            __syncthreads();
        }
        int run = sh[tid] - sum;
        for (int i = start; i < end; i++) { g_rowptr[i] = run; run += g_deg[i]; }
        if (end == n) g_rowptr[n] = run;
    } else {
        int i = (blockIdx.x - 1) * 256 + threadIdx.x;
        if (i < n) g_dinv[i] = rsqrtf((float)g_deg[i] + 1.0f);
    }
}

// ============ shared MMA compute for one 32-wide K chunk (BN=128) ============
__device__ __forceinline__ void compute_chunk(
    uint32_t aAhi, uint32_t aAlo, uint32_t aBhi, uint32_t aBlo,
    int warp_m, int warp_n, int lane, float acc[2][8][4])
{
    #pragma unroll
    for (int kk = 0; kk < 32; kk += 16) {
        uint32_t ah[2][4], al[2][4];
        #pragma unroll
        for (int mi = 0; mi < 2; mi++) {
            int row = warp_m * 32 + mi * 16 + (lane & 15);
            int col = kk + (lane >> 4) * 8;
            uint32_t off = (uint32_t)(row * SKEW + col) * 2;
            LDSM_X4(ah[mi][0], ah[mi][1], ah[mi][2], ah[mi][3], aAhi + off);
            LDSM_X4(al[mi][0], al[mi][1], al[mi][2], al[mi][3], aAlo + off);
        }
        uint32_t b[8][2];
        int g = lane >> 3;
        #pragma unroll
        for (int p = 0; p < 4; p++) {
            int nrow = warp_n * 64 + p * 16 + (g >> 1) * 8 + (lane & 7);
            int col = kk + (g & 1) * 8;
            uint32_t off = (uint32_t)(nrow * SKEW + col) * 2;
            uint32_t r0, r1, r2, r3;
            LDSM_X4(r0, r1, r2, r3, aBhi + off);
            b[p * 2][0] = r0; b[p * 2][1] = r1;
            b[p * 2 + 1][0] = r2; b[p * 2 + 1][1] = r3;
        }
        #pragma unroll
        for (int mi = 0; mi < 2; mi++)
            #pragma unroll
            for (int ni = 0; ni < 8; ni++) {
                MMA16816(acc[mi][ni], ah[mi], b[ni]);
                MMA16816(acc[mi][ni], al[mi], b[ni]);
            }
        #pragma unroll
        for (int p = 0; p < 4; p++) {
            int nrow = warp_n * 64 + p * 16 + (g >> 1) * 8 + (lane & 7);
            int col = kk + (g & 1) * 8;
            uint32_t off = (uint32_t)(nrow * SKEW + col) * 2;
            uint32_t r0, r1, r2, r3;
            LDSM_X4(r0, r1, r2, r3, aBlo + off);
            b[p * 2][0] = r0; b[p * 2][1] = r1;
            b[p * 2 + 1][0] = r2; b[p * 2 + 1][1] = r3;
        }
        #pragma unroll
        for (int mi = 0; mi < 2; mi++)
            #pragma unroll
            for (int ni = 0; ni < 8; ni++)
                MMA16816(acc[mi][ni], ah[mi], b[ni]);
    }
}

__device__ __forceinline__ void gemm_epilogue_to(float* __restrict__ dst,
                                                 float acc[2][8][4], int m0,
                                                 int warp_m, int warp_n, int lane, int M) {
    int gid = lane >> 2, tig = lane & 3;
    #pragma unroll
    for (int mi = 0; mi < 2; mi++) {
        #pragma unroll
        for (int ni = 0; ni < 8; ni++) {
            int col = warp_n * 64 + ni * 8 + tig * 2;
            int r0 = m0 + warp_m * 32 + mi * 16 + gid;
            if (r0 < M)
                *(float2*)(dst + (size_t)r0 * 128 + col) =
                    make_float2(acc[mi][ni][0], acc[mi][ni][1]);
            int r1 = r0 + 8;
            if (r1 < M)
                *(float2*)(dst + (size_t)r1 * 128 + col) =
                    make_float2(acc[mi][ni][2], acc[mi][ni][3]);
        }
    }
}

// ============ GEMM-1: reads x fp32 directly, splits on the fly ===============
__device__ void mma_gemm1_dev(char* smem, int bidx, const float* __restrict__ x, int M) {
    uint32_t sb = smem_u32(smem);
    int tid = threadIdx.x, wid = tid >> 5, lane = tid & 31;
    int m0 = bidx * 128;
    int warp_m = wid & 3, warp_n = wid >> 2;
    const int K = F0, nch = K >> 5;   // 8

    float acc[2][8][4] = {};
    float4 f[4];

    #define L1_LOADB(c) do { \
        uint32_t base = sb + 2 * TILE_B + ((c) & 1) * (2 * TILE_B); \
        _Pragma("unroll") \
        for (int it = 0; it < 2; it++) { \
            int id = it * 256 + tid; \
            int row = id >> 2, seg = id & 3; \
            uint32_t soff = (uint32_t)(row * SKEW + seg * 8) * 2; \
            CP_ASYNC16(base + soff,          g_W1thi + (size_t)row * K + ((c) << 5) + seg * 8, 16); \
            CP_ASYNC16(base + TILE_B + soff, g_W1tlo + (size_t)row * K + ((c) << 5) + seg * 8, 16); \
        } \
        CP_COMMIT; \
    } while (0)
    #define L1_LOADA(c) do { \
        _Pragma("unroll") \
        for (int it = 0; it < 4; it++) { \
            int id = it * 256 + tid; \
            int row = id >> 3, seg = id & 7; \
            int gr = m0 + row; \
            f[it] = (gr < M) ? *(const float4*)(x + (size_t)gr * K + ((c) << 5) + seg * 4) \
                             : make_float4(0.f, 0.f, 0.f, 0.f); \
        } \
    } while (0)

    L1_LOADB(0);
    L1_LOADA(0);

    for (int c = 0; c < nch; c++) {
        __syncthreads();
        if (c + 1 < nch) L1_LOADB(c + 1);
        #pragma unroll
        for (int it = 0; it < 4; it++) {
            int id = it * 256 + tid;
            int row = id >> 3, seg = id & 7;
            __nv_bfloat16 h0, h1, h2, h3, l0, l1, l2, l3;
            split1(f[it].x, h0, l0); split1(f[it].y, h1, l1);
            split1(f[it].z, h2, l2); split1(f[it].w, h3, l3);
            __nv_bfloat162 hp0; hp0.x = h0; hp0.y = h1;
            __nv_bfloat162 hp1; hp1.x = h2; hp1.y = h3;
            __nv_bfloat162 lp0; lp0.x = l0; lp0.y = l1;
            __nv_bfloat162 lp1; lp1.x = l2; lp1.y = l3;
            uint32_t soff = (uint32_t)(row * SKEW + seg * 4) * 2;
            *(uint2*)(smem + soff) = make_uint2(*(uint32_t*)&hp0, *(uint32_t*)&hp1);
            *(uint2*)(smem + TILE_B + soff) = make_uint2(*(uint32_t*)&lp0, *(uint32_t*)&lp1);
        }
        if (c + 1 < nch) { L1_LOADA(c + 1); CP_WAIT(1); }
        else             { CP_WAIT(0); }
        __syncthreads();

        uint32_t aBhi = sb + 2 * TILE_B + (c & 1) * (2 * TILE_B);
        compute_chunk(sb, sb + TILE_B, aBhi, aBhi + TILE_B, warp_m, warp_n, lane, acc);
    }
    gemm_epilogue_to(g_h, acc, m0, warp_m, warp_n, lane, M);
    #undef L1_LOADB
    #undef L1_LOADA
}

// ============ K2: GEMM-1 ∥ scatter ===========================================
__global__ void __launch_bounds__(256, 2) k2_gemm1_scatter(
    const float* __restrict__ x, const void* __restrict__ ei, int M, int E, int gemmB) {
    extern __shared__ char smem[];
    if (blockIdx.x < gemmB) {
        mma_gemm1_dev(smem, blockIdx.x, x, M);
    } else {
        int is64 = g_is64;
        int base = ((blockIdx.x - gemmB) * 256 + threadIdx.x) * 8;
        #pragma unroll
        for (int j = 0; j < 8; j++) {
            int i = base + j;
            if (i >= E) break;
            int s = load_edge(ei, i, is64);
            int d = load_edge(ei, (long long)E + i, is64);
            if ((unsigned)s >= (unsigned)NN || (unsigned)d >= (unsigned)NN) continue;
            int pos = g_rowptr[d] + g_slot[i];
            g_col[pos] = s;
            g_w[pos]   = g_dinv[s] * g_dinv[d];
        }
    }
}

// ============ agg phase: aggregate 128 rows into smem A chunks (bf16 hi/lo) ==
// Each warp handles 16 nodes. 4-way ILP gather. Writes zeros for rows >= n.
__device__ __forceinline__ void agg_to_smem(char* smem, const float* __restrict__ src,
                                            const float* __restrict__ bias,
                                            int m0, int n, int wid, int lane) {
    const float4* hv = (const float4*)src;
    float4 bb = ((const float4*)bias)[lane];
    int chunk = lane >> 3;
    int colin = (lane & 7) * 4;

    for (int t = 0; t < 16; t++) {
        int row = wid * 16 + t;
        int node = m0 + row;
        float4 r = make_float4(0.f, 0.f, 0.f, 0.f);
        if (node < n) {
            int beg = g_rowptr[node], end = g_rowptr[node + 1];
            float4 a0 = make_float4(0.f, 0.f, 0.f, 0.f), a1 = a0, a2 = a0, a3 = a0;
            int e = beg;
            for (; e + 4 <= end; e += 4) {
                int s0 = g_col[e],     s1 = g_col[e + 1];
                int s2 = g_col[e + 2], s3 = g_col[e + 3];
                float w0 = g_w[e],     w1 = g_w[e + 1];
                float w2 = g_w[e + 2], w3 = g_w[e + 3];
                float4 v0 = hv[(size_t)s0 * 32 + lane];
                float4 v1 = hv[(size_t)s1 * 32 + lane];
                float4 v2 = hv[(size_t)s2 * 32 + lane];
                float4 v3 = hv[(size_t)s3 * 32 + lane];
                a0.x += w0 * v0.x; a0.y += w0 * v0.y; a0.z += w0 * v0.z; a0.w += w0 * v0.w;
                a1.x += w1 * v1.x; a1.y += w1 * v1.y; a1.z += w1 * v1.z; a1.w += w1 * v1.w;
                a2.x += w2 * v2.x; a2.y += w2 * v2.y; a2.z += w2 * v2.z; a2.w += w2 * v2.w;
                a3.x += w3 * v3.x; a3.y += w3 * v3.y; a3.z += w3 * v3.z; a3.w += w3 * v3.w;
            }
            for (; e < end; e++) {
                int s0 = g_col[e];
                float w0 = g_w[e];
                float4 v0 = hv[(size_t)s0 * 32 + lane];
                a0.x += w0 * v0.x; a0.y += w0 * v0.y; a0.z += w0 * v0.z; a0.w += w0 * v0.w;
            }
            a0.x += a1.x + a2.x + a3.x;
            a0.y += a1.y + a2.y + a3.y;
            a0.z += a1.z + a2.z + a3.z;
            a0.w += a1.w + a2.w + a3.w;

            float di = g_dinv[node], di2 = di * di;
            float4 hs = hv[(size_t)node * 32 + lane];
            r.x = fmaxf(a0.x + di2 * hs.x + bb.x, 0.f);
            r.y = fmaxf(a0.y + di2 * hs.y + bb.y, 0.f);
            r.z = fmaxf(a0.z + di2 * hs.z + bb.z, 0.f);
            r.w = fmaxf(a0.w + di2 * hs.w + bb.w, 0.f);
        }
        __nv_bfloat16 h0, h1, h2, h3, l0, l1, l2, l3;
        split1(r.x, h0, l0); split1(r.y, h1, l1);
        split1(r.z, h2, l2); split1(r.w, h3, l3);
        __nv_bfloat162 hp0; hp0.x = h0; hp0.y = h1;
        __nv_bfloat162 hp1; hp1.x = h2; hp1.y = h3;
        __nv_bfloat162 lp0; lp0.x = l0; lp0.y = l1;
        __nv_bfloat162 lp1; lp1.x = l2; lp1.y = l3;
        uint32_t off = (uint32_t)(row * SKEW + colin) * 2;
        *(uint2*)(smem + chunk * TILE_B + off) =
            make_uint2(*(uint32_t*)&hp0, *(uint32_t*)&hp1);
        *(uint2*)(smem + 4 * TILE_B + chunk * TILE_B + off) =
            make_uint2(*(uint32_t*)&lp0, *(uint32_t*)&lp1);
    }
}

// ============ fused agg1 + GEMM-2: g_h2 = agg1(g_h) @ W2 =====================
__global__ void __launch_bounds__(256, 2) fused_agg_gemm2(const float* __restrict__ bias, int n) {
    extern __shared__ char smem[];
    uint32_t sb = smem_u32(smem);
    int tid = threadIdx.x, wid = tid >> 5, lane = tid & 31;
    int m0 = blockIdx.x * 128;
    int warp_m = wid & 3, warp_n = wid >> 2;

    // issue B chunk 0 (single buffer) before agg so it's resident by compute time
    #define L2_LOADB(c) do { \
        uint32_t base = sb + FUSED_BBASE; \
        _Pragma("unroll") \
        for (int it = 0; it < 2; it++) { \
            int id = it * 256 + tid; \
            int row = id >> 2, seg = id & 3; \
            uint32_t soff = (uint32_t)(row * SKEW + seg * 8) * 2; \
            CP_ASYNC16(base + soff,          g_W2thi + (size_t)row * FH + ((c) << 5) + seg * 8, 16); \
            CP_ASYNC16(base + TILE_B + soff, g_W2tlo + (size_t)row * FH + ((c) << 5) + seg * 8, 16); \
        } \
        CP_COMMIT; \
    } while (0)

    L2_LOADB(0);
    agg_to_smem(smem, g_h, bias, m0, n, wid, lane);
    __syncthreads();

    float acc[2][8][4] = {};
    const int nch = FH >> 5;   // 4
    for (int c = 0; c < nch; c++) {
        CP_WAIT(0);
        __syncthreads();
        uint32_t aB = sb + FUSED_BBASE;
        compute_chunk(sb + c * TILE_B, sb + 4 * TILE_B + c * TILE_B,
                      aB, aB + TILE_B, warp_m, warp_n, lane, acc);
        __syncthreads();
        if (c + 1 < nch) L2_LOADB(c + 1);
    }
    gemm_epilogue_to(g_h2, acc, m0, warp_m, warp_n, lane, n);
    #undef L2_LOADB
}

// ============ fused agg2 + classifier: out = agg2(g_h2) @ Wc + bc ============
__global__ void __launch_bounds__(256, 2) fused_agg_clf(const float* __restrict__ bias,
                                                        const float* __restrict__ bc,
                                                        float* __restrict__ out, int n) {
    extern __shared__ char smem[];
    uint32_t sb = smem_u32(smem);
    int tid = threadIdx.x, wid = tid >> 5, lane = tid & 31;
    int m0 = blockIdx.x * 128;
    int warp_m = wid & 3, warp_n = wid >> 2;   // warp tile 32x32 over N=64

    #define LC_LOADB(c) do { \
        uint32_t base = sb + FUSED_BBASE; \
        int row = tid >> 2, seg = tid & 3; \
        uint32_t soff = (uint32_t)(row * SKEW + seg * 8) * 2; \
        if (row < 64) { \
            CP_ASYNC16(base + soff,       g_Wcthi + (size_t)row * FH + ((c) << 5) + seg * 8, 16); \
            CP_ASYNC16(base + BCT + soff, g_Wctlo + (size_t)row * FH + ((c) << 5) + seg * 8, 16); \
        } \
        CP_COMMIT; \
    } while (0)

    LC_LOADB(0);
    agg_to_smem(smem, g_h2, bias, m0, n, wid, lane);
    __syncthreads();

    float acc[2][4][4] = {};
    const int nch = FH >> 5;   // 4
    for (int c = 0; c < nch; c++) {
        CP_WAIT(0);
        __syncthreads();
        uint32_t aAhi = sb + c * TILE_B;
        uint32_t aAlo = sb + 4 * TILE_B + c * TILE_B;
        uint32_t aBhi = sb + FUSED_BBASE, aBlo = aBhi + BCT;

        #pragma unroll
        for (int kk = 0; kk < 32; kk += 16) {
            uint32_t ah[2][4], al[2][4];
            #pragma unroll
            for (int mi = 0; mi < 2; mi++) {
                int row = warp_m * 32 + mi * 16 + (lane & 15);
                int col = kk + (lane >> 4) * 8;
                uint32_t off = (uint32_t)(row * SKEW + col) * 2;
                LDSM_X4(ah[mi][0], ah[mi][1], ah[mi][2], ah[mi][3], aAhi + off);
                LDSM_X4(al[mi][0], al[mi][1], al[mi][2], al[mi][3], aAlo + off);
            }
            uint32_t b[4][2];
            int g = lane >> 3;
            #pragma unroll
            for (int p = 0; p < 2; p++) {
                int nrow = warp_n * 32 + p * 16 + (g >> 1) * 8 + (lane & 7);
                int col = kk + (g & 1) * 8;
                uint32_t off = (uint32_t)(nrow * SKEW + col) * 2;
                uint32_t r0, r1, r2, r3;
                LDSM_X4(r0, r1, r2, r3, aBhi + off);
                b[p * 2][0] = r0; b[p * 2][1] = r1;
                b[p * 2 + 1][0] = r2; b[p * 2 + 1][1] = r3;
            }
            #pragma unroll
            for (int mi = 0; mi < 2; mi++)
                #pragma unroll
                for (int ni = 0; ni < 4; ni++) {
                    MMA16816(acc[mi][ni], ah[mi], b[ni]);
                    MMA16816(acc[mi][ni], al[mi], b[ni]);
                }
            #pragma unroll
            for (int p = 0; p < 2; p++) {
                int nrow = warp_n * 32 + p * 16 + (g >> 1) * 8 + (lane & 7);
                int col = kk + (g & 1) * 8;
                uint32_t off = (uint32_t)(nrow * SKEW + col) * 2;
                uint32_t r0, r1, r2, r3;
                LDSM_X4(r0, r1, r2, r3, aBlo + off);
                b[p * 2][0] = r0; b[p * 2][1] = r1;
                b[p * 2 + 1][0] = r2; b[p * 2 + 1][1] = r3;
            }
            #pragma unroll
            for (int mi = 0; mi < 2; mi++)
                #pragma unroll
                for (int ni = 0; ni < 4; ni++)
                    MMA16816(acc[mi][ni], ah[mi], b[ni]);
        }
        __syncthreads();
        if (c + 1 < nch) LC_LOADB(c + 1);
    }

    int gid = lane >> 2, tig = lane & 3;
    #pragma unroll
    for (int mi = 0; mi < 2; mi++) {
        #pragma unroll
        for (int ni = 0; ni < 4; ni++) {
            int col = warp_n * 32 + ni * 8 + tig * 2;
            if (col >= FC) continue;
            float b0 = bc[col], b1 = bc[col + 1];
            int r0 = m0 + warp_m * 32 + mi * 16 + gid;
            if (r0 < n)
                *(float2*)(out + (size_t)r0 * FC + col) =
                    make_float2(acc[mi][ni][0] + b0, acc[mi][ni][1] + b1);
            int r1 = r0 + 8;
            if (r1 < n)
                *(float2*)(out + (size_t)r1 * FC + col) =
                    make_float2(acc[mi][ni][2] + b0, acc[mi][ni][3] + b1);
        }
    }
    #undef LC_LOADB
}

// ---------------- launch ----------------
extern "C" void kernel_launch(void* const* d_in, const int* in_sizes, int n_in,
                              void* d_out, int out_size) {
    const float* x  = (const float*)d_in[0];
    const void*  ei = d_in[1];
    const float* W1 = (const float*)d_in[2];
    const float* b1 = (const float*)d_in[3];
    const float* W2 = (const float*)d_in[4];
    const float* b2 = (const float*)d_in[5];
    const float* Wc = (const float*)d_in[6];
    const float* bc = (const float*)d_in[7];
    float*       out = (float*)d_out;

    const int n = in_sizes[0] / F0;   // 100000
    const int E = in_sizes[1] / 2;    // 1600000

    cudaFuncSetAttribute(k2_gemm1_scatter, cudaFuncAttributeMaxDynamicSharedMemorySize, GSM_TOTAL);
    cudaFuncSetAttribute(fused_agg_gemm2, cudaFuncAttributeMaxDynamicSharedMemorySize, F2_SM_TOTAL);
    cudaFuncSetAttribute(fused_agg_clf, cudaFuncAttributeMaxDynamicSharedMemorySize, FC_SM_TOTAL);

    int zB    = (n + 255) / 256;
    int bDeg  = (E + 1023) / 1024;
    int bW1   = (F0 * FH + 255) / 256;
    int bW2   = (FH * FH + 255) / 256;
    int bWc   = (64 * FH + 255) / 256;
    int gemmB = (n + 127) / 128;
    int scatB = (E + 2047) / 2048;
    int dinvB = (n + 255) / 256;

    k0_detect_zero<<<1 + zB, 256>>>((const int*)ei, 2 * E, n);
    k1_prep<<<bDeg + bW1 + bW2 + bWc, 256>>>(ei, E, W1, W2, Wc, bDeg, bW1, bW2);
    k1b_scan_dinv<<<1 + dinvB, 256>>>(n);
    k2_gemm1_scatter<<<gemmB + scatB, 256, GSM_TOTAL>>>(x, ei, n, E, gemmB);
    fused_agg_gemm2<<<gemmB, 256, F2_SM_TOTAL>>>(b1, n);
    fused_agg_clf<<<gemmB, 256, FC_SM_TOTAL>>>(b2, bc, out, n);
}

// round 13
// speedup vs baseline: 1.2803x; 1.2803x over previous
#include <cuda_runtime.h>
#include <cuda_bf16.h>
#include <cstdint>

#define NN 100000
#define EE 1600000
#define F0 256
#define FH 128
#define FC 40

// ---------------- static device scratch ----------------
__device__ float g_h[(size_t)NN * FH];
__device__ int   g_deg[NN];
__device__ float g_dinv[NN];
__device__ int   g_rowptr[NN + 1];
__device__ int   g_col[EE];
__device__ int   g_slot[EE];
__device__ float g_w[EE];
__device__ int   g_is64;
__device__ __nv_bfloat16 g_Ahi[(size_t)NN * FH];   // layer-2 input (from agg1)
__device__ __nv_bfloat16 g_Alo[(size_t)NN * FH];
__device__ __nv_bfloat16 g_W1thi[FH * F0], g_W1tlo[FH * F0];   // [128][256] K-major
__device__ __nv_bfloat16 g_W2thi[FH * FH], g_W2tlo[FH * FH];   // [128][128] K-major
__device__ __nv_bfloat16 g_Wcthi[64 * FH], g_Wctlo[64 * FH];   // [64(pad40)][128] K-major

// ---------------- helpers ----------------
__device__ __forceinline__ uint32_t smem_u32(const void* p) {
    uint32_t a;
    asm("{ .reg .u64 t; cvta.to.shared.u64 t, %1; cvt.u32.u64 %0, t; }" : "=r"(a) : "l"(p));
    return a;
}
#define LDSM_X4(r0, r1, r2, r3, addr) \
    asm volatile("ldmatrix.sync.aligned.m8n8.x4.shared.b16 {%0,%1,%2,%3}, [%4];" \
                 : "=r"(r0), "=r"(r1), "=r"(r2), "=r"(r3) : "r"(addr))
#define MMA16816(d, a, b) \
    asm volatile("mma.sync.aligned.m16n8k16.row.col.f32.bf16.bf16.f32 " \
                 "{%0,%1,%2,%3}, {%4,%5,%6,%7}, {%8,%9}, {%0,%1,%2,%3};" \
                 : "+f"((d)[0]), "+f"((d)[1]), "+f"((d)[2]), "+f"((d)[3]) \
                 : "r"((a)[0]), "r"((a)[1]), "r"((a)[2]), "r"((a)[3]), \
                   "r"((b)[0]), "r"((b)[1]))
#define CP_ASYNC16(dst, src, sz) \
    asm volatile("cp.async.cg.shared.global [%0], [%1], 16, %2;" \
                 :: "r"(dst), "l"(src), "r"(sz) : "memory")
#define CP_COMMIT asm volatile("cp.async.commit_group;" ::: "memory")
#define CP_WAIT(n) asm volatile("cp.async.wait_group %0;" :: "n"(n) : "memory")

__device__ __forceinline__ int load_edge(const void* ei, long long idx, int is64) {
    if (is64) return (int)((const long long*)ei)[idx];
    return ((const int*)ei)[idx];
}
__device__ __forceinline__ void split1(float f, __nv_bfloat16& hi, __nv_bfloat16& lo) {
    hi = __float2bfloat16(f);
    lo = __float2bfloat16(f - __bfloat162float(hi));
}

#define SKEW 40
#define TILE_B (128 * SKEW * 2)     // 10240 bytes
#define STAGE_B (4 * TILE_B)
#define GSM_TOTAL (2 * STAGE_B)     // 81920

// ================= K0: detect dtype + zero deg ===============================
__global__ void k0_detect_zero(const int* __restrict__ ei32, int total_words, int n) {
    if (blockIdx.x == 0) {
        __shared__ int acc;
        if (threadIdx.x == 0) acc = 0;
        __syncthreads();
        int v = 0;
        int lim = min(total_words, 8192);
        for (int i = 1 + 2 * threadIdx.x; i < lim; i += 2 * blockDim.x) v |= ei32[i];
        if (v) atomicOr(&acc, 1);
        __syncthreads();
        if (threadIdx.x == 0) g_is64 = (acc == 0) ? 1 : 0;
    } else {
        int i = (blockIdx.x - 1) * blockDim.x + threadIdx.x;
        if (i < n) g_deg[i] = 0;
    }
}

// ====== K1: deg+slot ∥ split_wt1 ∥ split_wt2 ∥ split_wc ======================
__global__ void k1_prep(const void* __restrict__ ei, int E,
                        const float* __restrict__ W1, const float* __restrict__ W2,
                        const float* __restrict__ Wc,
                        int bDeg, int bW1, int bW2) {
    int b = blockIdx.x, tid = threadIdx.x;
    if (b < bDeg) {
        int is64 = g_is64;
        int base = (b * 256 + tid) * 4;
        #pragma unroll
        for (int j = 0; j < 4; j++) {
            int i = base + j;
            if (i < E) {
                int d = load_edge(ei, (long long)E + i, is64);
                if ((unsigned)d < (unsigned)NN)
                    g_slot[i] = atomicAdd(&g_deg[d], 1);
            }
        }
    } else if (b < bDeg + bW1) {
        int i = (b - bDeg) * 256 + tid;
        if (i < F0 * FH) {
            int k = i / FH, nidx = i % FH;
            __nv_bfloat16 hi, lo;
            split1(W1[i], hi, lo);
            g_W1thi[nidx * F0 + k] = hi;
            g_W1tlo[nidx * F0 + k] = lo;
        }
    } else if (b < bDeg + bW1 + bW2) {
        int i = (b - bDeg - bW1) * 256 + tid;
        if (i < FH * FH) {
            int k = i / FH, nidx = i % FH;
            __nv_bfloat16 hi, lo;
            split1(W2[i], hi, lo);
            g_W2thi[nidx * FH + k] = hi;
            g_W2tlo[nidx * FH + k] = lo;
        }
    } else {
        int i = (b - bDeg - bW1 - bW2) * 256 + tid;
        if (i < 64 * FH) {
            int nidx = i / FH, k = i % FH;
            float f = (nidx < FC) ? Wc[k * FC + nidx] : 0.f;
            __nv_bfloat16 hi, lo;
            split1(f, hi, lo);
            g_Wcthi[nidx * FH + k] = hi;
            g_Wctlo[nidx * FH + k] = lo;
        }
    }
}

// ====== K1b: exclusive scan (block 0) ∥ dinv =================================
__global__ void k1b_scan_dinv(int n) {
    if (blockIdx.x == 0) {
        __shared__ int sh[256];
        int tid = threadIdx.x;
        int chunk = (n + 255) >> 8;
        int start = tid * chunk, end = min(start + chunk, n);
        int sum = 0;
        for (int i = start; i < end; i++) sum += g_deg[i];
        sh[tid] = sum;
        __syncthreads();
        for (int off = 1; off < 256; off <<= 1) {
            int v = 0;
            if (tid >= off) v = sh[tid - off];
            __syncthreads();
            sh[tid] += v;
            __syncthreads();
        }
        int run = sh[tid] - sum;
        for (int i = start; i < end; i++) { g_rowptr[i] = run; run += g_deg[i]; }
        if (end == n) g_rowptr[n] = run;
    } else {
        int i = (blockIdx.x - 1) * 256 + threadIdx.x;
        if (i < n) g_dinv[i] = rsqrtf((float)g_deg[i] + 1.0f);
    }
}

// ============ shared MMA compute for one 32-wide K chunk =====================
__device__ __forceinline__ void compute_chunk(
    uint32_t aAhi, uint32_t aAlo, uint32_t aBhi, uint32_t aBlo,
    int warp_m, int warp_n, int lane, float acc[2][8][4])
{
    #pragma unroll
    for (int kk = 0; kk < 32; kk += 16) {
        uint32_t ah[2][4], al[2][4];
        #pragma unroll
        for (int mi = 0; mi < 2; mi++) {
            int row = warp_m * 32 + mi * 16 + (lane & 15);
            int col = kk + (lane >> 4) * 8;
            uint32_t off = (uint32_t)(row * SKEW + col) * 2;
            LDSM_X4(ah[mi][0], ah[mi][1], ah[mi][2], ah[mi][3], aAhi + off);
            LDSM_X4(al[mi][0], al[mi][1], al[mi][2], al[mi][3], aAlo + off);
        }
        uint32_t b[8][2];
        int g = lane >> 3;
        #pragma unroll
        for (int p = 0; p < 4; p++) {
            int nrow = warp_n * 64 + p * 16 + (g >> 1) * 8 + (lane & 7);
            int col = kk + (g & 1) * 8;
            uint32_t off = (uint32_t)(nrow * SKEW + col) * 2;
            uint32_t r0, r1, r2, r3;
            LDSM_X4(r0, r1, r2, r3, aBhi + off);
            b[p * 2][0] = r0; b[p * 2][1] = r1;
            b[p * 2 + 1][0] = r2; b[p * 2 + 1][1] = r3;
        }
        #pragma unroll
        for (int mi = 0; mi < 2; mi++)
            #pragma unroll
            for (int ni = 0; ni < 8; ni++) {
                MMA16816(acc[mi][ni], ah[mi], b[ni]);
                MMA16816(acc[mi][ni], al[mi], b[ni]);
            }
        #pragma unroll
        for (int p = 0; p < 4; p++) {
            int nrow = warp_n * 64 + p * 16 + (g >> 1) * 8 + (lane & 7);
            int col = kk + (g & 1) * 8;
            uint32_t off = (uint32_t)(nrow * SKEW + col) * 2;
            uint32_t r0, r1, r2, r3;
            LDSM_X4(r0, r1, r2, r3, aBlo + off);
            b[p * 2][0] = r0; b[p * 2][1] = r1;
            b[p * 2 + 1][0] = r2; b[p * 2 + 1][1] = r3;
        }
        #pragma unroll
        for (int mi = 0; mi < 2; mi++)
            #pragma unroll
            for (int ni = 0; ni < 8; ni++)
                MMA16816(acc[mi][ni], ah[mi], b[ni]);
    }
}

__device__ __forceinline__ void gemm_epilogue(float acc[2][8][4], int m0,
                                              int warp_m, int warp_n, int lane, int M) {
    int gid = lane >> 2, tig = lane & 3;
    #pragma unroll
    for (int mi = 0; mi < 2; mi++) {
        #pragma unroll
        for (int ni = 0; ni < 8; ni++) {
            int col = warp_n * 64 + ni * 8 + tig * 2;
            int r0 = m0 + warp_m * 32 + mi * 16 + gid;
            if (r0 < M)
                *(float2*)(g_h + (size_t)r0 * 128 + col) =
                    make_float2(acc[mi][ni][0], acc[mi][ni][1]);
            int r1 = r0 + 8;
            if (r1 < M)
                *(float2*)(g_h + (size_t)r1 * 128 + col) =
                    make_float2(acc[mi][ni][2], acc[mi][ni][3]);
        }
    }
}

// ============ GEMM-1: reads x fp32 directly, splits on the fly ===============
__device__ void mma_gemm1_dev(char* smem, int bidx, const float* __restrict__ x, int M) {
    uint32_t sb = smem_u32(smem);
    int tid = threadIdx.x, wid = tid >> 5, lane = tid & 31;
    int m0 = bidx * 128;
    int warp_m = wid & 3, warp_n = wid >> 2;
    const int K = F0, nch = K >> 5;   // 8

    float acc[2][8][4] = {};
    float4 f[4];

    #define L1_LOADB(c) do { \
        uint32_t base = sb + 2 * TILE_B + ((c) & 1) * (2 * TILE_B); \
        _Pragma("unroll") \
        for (int it = 0; it < 2; it++) { \
            int id = it * 256 + tid; \
            int row = id >> 2, seg = id & 3; \
            uint32_t soff = (uint32_t)(row * SKEW + seg * 8) * 2; \
            CP_ASYNC16(base + soff,          g_W1thi + (size_t)row * K + ((c) << 5) + seg * 8, 16); \
            CP_ASYNC16(base + TILE_B + soff, g_W1tlo + (size_t)row * K + ((c) << 5) + seg * 8, 16); \
        } \
        CP_COMMIT; \
    } while (0)
    #define L1_LOADA(c) do { \
        _Pragma("unroll") \
        for (int it = 0; it < 4; it++) { \
            int id = it * 256 + tid; \
            int row = id >> 3, seg = id & 7; \
            int gr = m0 + row; \
            f[it] = (gr < M) ? *(const float4*)(x + (size_t)gr * K + ((c) << 5) + seg * 4) \
                             : make_float4(0.f, 0.f, 0.f, 0.f); \
        } \
    } while (0)

    L1_LOADB(0);
    L1_LOADA(0);

    for (int c = 0; c < nch; c++) {
        __syncthreads();   // all prior reads of A smem & B[(c+1)&1] complete
        if (c + 1 < nch) L1_LOADB(c + 1);
        #pragma unroll
        for (int it = 0; it < 4; it++) {
            int id = it * 256 + tid;
            int row = id >> 3, seg = id & 7;
            __nv_bfloat16 h0, h1, h2, h3, l0, l1, l2, l3;
            split1(f[it].x, h0, l0); split1(f[it].y, h1, l1);
            split1(f[it].z, h2, l2); split1(f[it].w, h3, l3);
            __nv_bfloat162 hp0; hp0.x = h0; hp0.y = h1;
            __nv_bfloat162 hp1; hp1.x = h2; hp1.y = h3;
            __nv_bfloat162 lp0; lp0.x = l0; lp0.y = l1;
            __nv_bfloat162 lp1; lp1.x = l2; lp1.y = l3;
            uint32_t soff = (uint32_t)(row * SKEW + seg * 4) * 2;
            *(uint2*)(smem + soff) = make_uint2(*(uint32_t*)&hp0, *(uint32_t*)&hp1);
            *(uint2*)(smem + TILE_B + soff) = make_uint2(*(uint32_t*)&lp0, *(uint32_t*)&lp1);
        }
        if (c + 1 < nch) { L1_LOADA(c + 1); CP_WAIT(1); }
        else             { CP_WAIT(0); }
        __syncthreads();

        uint32_t aBhi = sb + 2 * TILE_B + (c & 1) * (2 * TILE_B);
        compute_chunk(sb, sb + TILE_B, aBhi, aBhi + TILE_B, warp_m, warp_n, lane, acc);
    }
    gemm_epilogue(acc, m0, warp_m, warp_n, lane, M);
    #undef L1_LOADB
    #undef L1_LOADA
}

// ============ GEMM-2: bf16 A from g_Ahi/g_Alo (cp.async 2-stage) =============
__device__ __forceinline__ void gemm2_load_stage(uint32_t sbase, int m0, int kc, int M) {
    int tid = threadIdx.x;
    #pragma unroll
    for (int it = 0; it < 2; it++) {
        int id = it * 256 + tid;
        int row = id >> 2, seg = id & 3;
        uint32_t soff = (uint32_t)(row * SKEW + seg * 8) * 2;
        int gr = m0 + row;
        int ok = (gr < M) ? 16 : 0;
        size_t grc = (gr < M) ? (size_t)gr : 0;
        CP_ASYNC16(sbase + soff,              g_Ahi + grc * FH + kc + seg * 8, ok);
        CP_ASYNC16(sbase + TILE_B + soff,     g_Alo + grc * FH + kc + seg * 8, ok);
        CP_ASYNC16(sbase + 2 * TILE_B + soff, g_W2thi + (size_t)row * FH + kc + seg * 8, 16);
        CP_ASYNC16(sbase + 3 * TILE_B + soff, g_W2tlo + (size_t)row * FH + kc + seg * 8, 16);
    }
}

__global__ void __launch_bounds__(256, 2) mma_gemm2(int M) {
    extern __shared__ char smem[];
    uint32_t sb = smem_u32(smem);
    int tid = threadIdx.x, wid = tid >> 5, lane = tid & 31;
    int m0 = blockIdx.x * 128;
    int warp_m = wid & 3, warp_n = wid >> 2;

    float acc[2][8][4] = {};
    const int nch = FH >> 5;   // 4

    gemm2_load_stage(sb, m0, 0, M);
    CP_COMMIT;
    for (int c = 0; c < nch; c++) {
        if (c + 1 < nch) {
            gemm2_load_stage(sb + ((c + 1) & 1) * STAGE_B, m0, (c + 1) << 5, M);
            CP_COMMIT;
            CP_WAIT(1);
        } else {
            CP_WAIT(0);
        }
        __syncthreads();
        uint32_t stg = sb + (c & 1) * STAGE_B;
        compute_chunk(stg, stg + TILE_B, stg + 2 * TILE_B, stg + 3 * TILE_B,
                      warp_m, warp_n, lane, acc);
        __syncthreads();
    }
    gemm_epilogue(acc, m0, warp_m, warp_n, lane, M);
}

// ============ K2: GEMM-1 ∥ scatter ===========================================
__global__ void __launch_bounds__(256, 2) k2_gemm1_scatter(
    const float* __restrict__ x, const void* __restrict__ ei, int M, int E, int gemmB) {
    extern __shared__ char smem[];
    if (blockIdx.x < gemmB) {
        mma_gemm1_dev(smem, blockIdx.x, x, M);
    } else {
        int is64 = g_is64;
        int base = ((blockIdx.x - gemmB) * 256 + threadIdx.x) * 8;
        #pragma unroll
        for (int j = 0; j < 8; j++) {
            int i = base + j;
            if (i >= E) break;
            int s = load_edge(ei, i, is64);
            int d = load_edge(ei, (long long)E + i, is64);
            if ((unsigned)s >= (unsigned)NN || (unsigned)d >= (unsigned)NN) continue;
            int pos = g_rowptr[d] + g_slot[i];
            g_col[pos] = s;
            g_w[pos]   = g_dinv[s] * g_dinv[d];
        }
    }
}

// ---------------- aggregation: warp per node, 4-way ILP, bf16 hi/lo out ------
__global__ void agg_kernel(const float* __restrict__ bias, int n) {
    int warp = (blockIdx.x * blockDim.x + threadIdx.x) >> 5;
    if (warp >= n) return;
    int lane = threadIdx.x & 31;
    int beg = g_rowptr[warp], end = g_rowptr[warp + 1];
    const float4* hv = (const float4*)g_h;

    float4 a0 = make_float4(0.f, 0.f, 0.f, 0.f), a1 = a0, a2 = a0, a3 = a0;
    int e = beg;
    for (; e + 4 <= end; e += 4) {
        int s0 = g_col[e],     s1 = g_col[e + 1];
        int s2 = g_col[e + 2], s3 = g_col[e + 3];
        float w0 = g_w[e],     w1 = g_w[e + 1];
        float w2 = g_w[e + 2], w3 = g_w[e + 3];
        float4 v0 = hv[(size_t)s0 * 32 + lane];
        float4 v1 = hv[(size_t)s1 * 32 + lane];
        float4 v2 = hv[(size_t)s2 * 32 + lane];
        float4 v3 = hv[(size_t)s3 * 32 + lane];
        a0.x += w0 * v0.x; a0.y += w0 * v0.y; a0.z += w0 * v0.z; a0.w += w0 * v0.w;
        a1.x += w1 * v1.x; a1.y += w1 * v1.y; a1.z += w1 * v1.z; a1.w += w1 * v1.w;
        a2.x += w2 * v2.x; a2.y += w2 * v2.y; a2.z += w2 * v2.z; a2.w += w2 * v2.w;
        a3.x += w3 * v3.x; a3.y += w3 * v3.y; a3.z += w3 * v3.z; a3.w += w3 * v3.w;
    }
    for (; e < end; e++) {
        int s0 = g_col[e];
        float w0 = g_w[e];
        float4 v0 = hv[(size_t)s0 * 32 + lane];
        a0.x += w0 * v0.x; a0.y += w0 * v0.y; a0.z += w0 * v0.z; a0.w += w0 * v0.w;
    }
    a0.x += a1.x + a2.x + a3.x;
    a0.y += a1.y + a2.y + a3.y;
    a0.z += a1.z + a2.z + a3.z;
    a0.w += a1.w + a2.w + a3.w;

    float di = g_dinv[warp], di2 = di * di;
    float4 hs = hv[(size_t)warp * 32 + lane];
    float4 bb = ((const float4*)bias)[lane];
    float4 r;
    r.x = fmaxf(a0.x + di2 * hs.x + bb.x, 0.f);
    r.y = fmaxf(a0.y + di2 * hs.y + bb.y, 0.f);
    r.z = fmaxf(a0.z + di2 * hs.z + bb.z, 0.f);
    r.w = fmaxf(a0.w + di2 * hs.w + bb.w, 0.f);

    __nv_bfloat16 h0, h1, h2, h3, l0, l1, l2, l3;
    split1(r.x, h0, l0); split1(r.y, h1, l1);
    split1(r.z, h2, l2); split1(r.w, h3, l3);
    __nv_bfloat162 hp0; hp0.x = h0; hp0.y = h1;
    __nv_bfloat162 hp1; hp1.x = h2; hp1.y = h3;
    __nv_bfloat162 lp0; lp0.x = l0; lp0.y = l1;
    __nv_bfloat162 lp1; lp1.x = l2; lp1.y = l3;
    size_t idx2 = (size_t)warp * 64 + lane * 2;
    ((__nv_bfloat162*)g_Ahi)[idx2] = hp0;
    ((__nv_bfloat162*)g_Ahi)[idx2 + 1] = hp1;
    ((__nv_bfloat162*)g_Alo)[idx2] = lp0;
    ((__nv_bfloat162*)g_Alo)[idx2 + 1] = lp1;
}

// ============ classifier: bf16 HMMA, BM=128 BN=64(40) K=128, 3-term ==========
#define CTILE_A (128 * SKEW * 2)
#define CTILE_Bc (64 * SKEW * 2)
#define CSTAGE (2 * CTILE_A + 2 * CTILE_Bc)
#define CSM_TOTAL (2 * CSTAGE)

__device__ __forceinline__ void clf_load_stage(uint32_t sbase, int m0, int kc, int M) {
    int tid = threadIdx.x;
    #pragma unroll
    for (int it = 0; it < 2; it++) {
        int id = it * 256 + tid;
        int row = id >> 2, seg = id & 3;
        uint32_t soff = (uint32_t)(row * SKEW + seg * 8) * 2;
        int gr = m0 + row;
        int ok = (gr < M) ? 16 : 0;
        size_t grc = (gr < M) ? (size_t)gr : 0;
        CP_ASYNC16(sbase + soff,           g_Ahi + grc * FH + kc + seg * 8, ok);
        CP_ASYNC16(sbase + CTILE_A + soff, g_Alo + grc * FH + kc + seg * 8, ok);
    }
    {
        int row = tid >> 2, seg = tid & 3;
        uint32_t soff = (uint32_t)(row * SKEW + seg * 8) * 2;
        CP_ASYNC16(sbase + 2 * CTILE_A + soff,            g_Wcthi + (size_t)row * FH + kc + seg * 8, 16);
        CP_ASYNC16(sbase + 2 * CTILE_A + CTILE_Bc + soff, g_Wctlo + (size_t)row * FH + kc + seg * 8, 16);
    }
}

__global__ void __launch_bounds__(256, 2) mma_clf(const float* __restrict__ bias,
                                                  float* __restrict__ out, int M) {
    extern __shared__ char smem[];
    uint32_t sb = smem_u32(smem);
    int tid = threadIdx.x, wid = tid >> 5, lane = tid & 31;
    int m0 = blockIdx.x * 128;
    int warp_m = wid & 3, warp_n = wid >> 2;

    float acc[2][4][4] = {};
    const int nch = FH >> 5;

    clf_load_stage(sb, m0, 0, M);
    CP_COMMIT;
    for (int c = 0; c < nch; c++) {
        if (c + 1 < nch) {
            clf_load_stage(sb + ((c + 1) & 1) * CSTAGE, m0, (c + 1) << 5, M);
            CP_COMMIT;
            CP_WAIT(1);
        } else {
            CP_WAIT(0);
        }
        __syncthreads();

        uint32_t stg = sb + (c & 1) * CSTAGE;
        uint32_t aAhi = stg, aAlo = stg + CTILE_A;
        uint32_t aBhi = stg + 2 * CTILE_A, aBlo = aBhi + CTILE_Bc;

        #pragma unroll
        for (int kk = 0; kk < 32; kk += 16) {
            uint32_t ah[2][4], al[2][4];
            #pragma unroll
            for (int mi = 0; mi < 2; mi++) {
                int row = warp_m * 32 + mi * 16 + (lane & 15);
                int col = kk + (lane >> 4) * 8;
                uint32_t off = (uint32_t)(row * SKEW + col) * 2;
                LDSM_X4(ah[mi][0], ah[mi][1], ah[mi][2], ah[mi][3], aAhi + off);
                LDSM_X4(al[mi][0], al[mi][1], al[mi][2], al[mi][3], aAlo + off);
            }
            uint32_t b[4][2];
            int g = lane >> 3;
            #pragma unroll
            for (int p = 0; p < 2; p++) {
                int nrow = warp_n * 32 + p * 16 + (g >> 1) * 8 + (lane & 7);
                int col = kk + (g & 1) * 8;
                uint32_t off = (uint32_t)(nrow * SKEW + col) * 2;
                uint32_t r0, r1, r2, r3;
                LDSM_X4(r0, r1, r2, r3, aBhi + off);
                b[p * 2][0] = r0; b[p * 2][1] = r1;
                b[p * 2 + 1][0] = r2; b[p * 2 + 1][1] = r3;
            }
            #pragma unroll
            for (int mi = 0; mi < 2; mi++)
                #pragma unroll
                for (int ni = 0; ni < 4; ni++) {
                    MMA16816(acc[mi][ni], ah[mi], b[ni]);
                    MMA16816(acc[mi][ni], al[mi], b[ni]);
                }
            #pragma unroll
            for (int p = 0; p < 2; p++) {
                int nrow = warp_n * 32 + p * 16 + (g >> 1) * 8 + (lane & 7);
                int col = kk + (g & 1) * 8;
                uint32_t off = (uint32_t)(nrow * SKEW + col) * 2;
                uint32_t r0, r1, r2, r3;
                LDSM_X4(r0, r1, r2, r3, aBlo + off);
                b[p * 2][0] = r0; b[p * 2][1] = r1;
                b[p * 2 + 1][0] = r2; b[p * 2 + 1][1] = r3;
            }
            #pragma unroll
            for (int mi = 0; mi < 2; mi++)
                #pragma unroll
                for (int ni = 0; ni < 4; ni++)
                    MMA16816(acc[mi][ni], ah[mi], b[ni]);
        }
        __syncthreads();
    }

    int gid = lane >> 2, tig = lane & 3;
    #pragma unroll
    for (int mi = 0; mi < 2; mi++) {
        #pragma unroll
        for (int ni = 0; ni < 4; ni++) {
            int col = warp_n * 32 + ni * 8 + tig * 2;
            if (col >= FC) continue;
            float b0 = bias[col], b1 = bias[col + 1];
            int r0 = m0 + warp_m * 32 + mi * 16 + gid;
            if (r0 < M)
                *(float2*)(out + (size_t)r0 * FC + col) =
                    make_float2(acc[mi][ni][0] + b0, acc[mi][ni][1] + b1);
            int r1 = r0 + 8;
            if (r1 < M)
                *(float2*)(out + (size_t)r1 * FC + col) =
                    make_float2(acc[mi][ni][2] + b0, acc[mi][ni][3] + b1);
        }
    }
}

// ---------------- launch ----------------
extern "C" void kernel_launch(void* const* d_in, const int* in_sizes, int n_in,
                              void* d_out, int out_size) {
    const float* x  = (const float*)d_in[0];
    const void*  ei = d_in[1];
    const float* W1 = (const float*)d_in[2];
    const float* b1 = (const float*)d_in[3];
    const float* W2 = (const float*)d_in[4];
    const float* b2 = (const float*)d_in[5];
    const float* Wc = (const float*)d_in[6];
    const float* bc = (const float*)d_in[7];
    float*       out = (float*)d_out;

    const int n = in_sizes[0] / F0;   // 100000
    const int E = in_sizes[1] / 2;    // 1600000

    cudaFuncSetAttribute(k2_gemm1_scatter, cudaFuncAttributeMaxDynamicSharedMemorySize, GSM_TOTAL);
    cudaFuncSetAttribute(mma_gemm2, cudaFuncAttributeMaxDynamicSharedMemorySize, GSM_TOTAL);
    cudaFuncSetAttribute(mma_clf, cudaFuncAttributeMaxDynamicSharedMemorySize, CSM_TOTAL);

    int zB    = (n + 255) / 256;
    int bDeg  = (E + 1023) / 1024;
    int bW1   = (F0 * FH + 255) / 256;
    int bW2   = (FH * FH + 255) / 256;
    int bWc   = (64 * FH + 255) / 256;
    int gemmB = (n + 127) / 128;
    int scatB = (E + 2047) / 2048;
    int dinvB = (n + 255) / 256;

    k0_detect_zero<<<1 + zB, 256>>>((const int*)ei, 2 * E, n);
    k1_prep<<<bDeg + bW1 + bW2 + bWc, 256>>>(ei, E, W1, W2, Wc, bDeg, bW1, bW2);
    k1b_scan_dinv<<<1 + dinvB, 256>>>(n);
    k2_gemm1_scatter<<<gemmB + scatB, 256, GSM_TOTAL>>>(x, ei, n, E, gemmB);
    agg_kernel<<<(n + 7) / 8, 256>>>(b1, n);
    mma_gemm2<<<gemmB, 256, GSM_TOTAL>>>(n);
    agg_kernel<<<(n + 7) / 8, 256>>>(b2, n);
    mma_clf<<<gemmB, 256, CSM_TOTAL>>>(bc, out, n);
}

// round 14
// speedup vs baseline: 1.3208x; 1.0316x over previous
#include <cuda_runtime.h>
#include <cuda_bf16.h>
#include <cstdint>

#define NN 100000
#define EE 1600000
#define F0 256
#define FH 128
#define FC 40

// ---------------- static device scratch ----------------
__device__ float g_h[(size_t)NN * FH];
__device__ int   g_deg[NN];
__device__ float g_dinv[NN];
__device__ int   g_rowptr[NN + 1];
__device__ int   g_col[EE];
__device__ int   g_slot[EE];
__device__ int   g_is64;
__device__ __nv_bfloat16 g_Ahi[(size_t)NN * FH];   // layer-2 input (from agg1)
__device__ __nv_bfloat16 g_Alo[(size_t)NN * FH];
__device__ __nv_bfloat16 g_W1thi[FH * F0], g_W1tlo[FH * F0];   // [128][256] K-major
__device__ __nv_bfloat16 g_W2thi[FH * FH], g_W2tlo[FH * FH];   // [128][128] K-major
__device__ __nv_bfloat16 g_Wcthi[64 * FH], g_Wctlo[64 * FH];   // [64(pad40)][128] K-major

// ---------------- helpers ----------------
__device__ __forceinline__ uint32_t smem_u32(const void* p) {
    uint32_t a;
    asm("{ .reg .u64 t; cvta.to.shared.u64 t, %1; cvt.u32.u64 %0, t; }" : "=r"(a) : "l"(p));
    return a;
}
#define LDSM_X4(r0, r1, r2, r3, addr) \
    asm volatile("ldmatrix.sync.aligned.m8n8.x4.shared.b16 {%0,%1,%2,%3}, [%4];" \
                 : "=r"(r0), "=r"(r1), "=r"(r2), "=r"(r3) : "r"(addr))
#define MMA16816(d, a, b) \
    asm volatile("mma.sync.aligned.m16n8k16.row.col.f32.bf16.bf16.f32 " \
                 "{%0,%1,%2,%3}, {%4,%5,%6,%7}, {%8,%9}, {%0,%1,%2,%3};" \
                 : "+f"((d)[0]), "+f"((d)[1]), "+f"((d)[2]), "+f"((d)[3]) \
                 : "r"((a)[0]), "r"((a)[1]), "r"((a)[2]), "r"((a)[3]), \
                   "r"((b)[0]), "r"((b)[1]))
#define CP_ASYNC16(dst, src, sz) \
    asm volatile("cp.async.cg.shared.global [%0], [%1], 16, %2;" \
                 :: "r"(dst), "l"(src), "r"(sz) : "memory")
#define CP_COMMIT asm volatile("cp.async.commit_group;" ::: "memory")
#define CP_WAIT(n) asm volatile("cp.async.wait_group %0;" :: "n"(n) : "memory")

__device__ __forceinline__ int load_edge(const void* ei, long long idx, int is64) {
    if (is64) return (int)((const long long*)ei)[idx];
    return ((const int*)ei)[idx];
}
__device__ __forceinline__ void split1(float f, __nv_bfloat16& hi, __nv_bfloat16& lo) {
    hi = __float2bfloat16(f);
    lo = __float2bfloat16(f - __bfloat162float(hi));
}

#define SKEW 40
#define TILE_B (128 * SKEW * 2)     // 10240 bytes
#define STAGE_B (4 * TILE_B)
#define GSM_TOTAL (2 * STAGE_B)     // 81920

// ============ K0: detect ∥ zero deg ∥ split W1/W2/Wc =========================
__global__ void k0_prep(const int* __restrict__ ei32, int total_words, int n,
                        const float* __restrict__ W1, const float* __restrict__ W2,
                        const float* __restrict__ Wc, int zB, int bW1, int bW2) {
    int b = blockIdx.x, tid = threadIdx.x;
    if (b == 0) {
        __shared__ int acc;
        if (tid == 0) acc = 0;
        __syncthreads();
        int v = 0;
        int lim = min(total_words, 8192);
        for (int i = 1 + 2 * tid; i < lim; i += 2 * blockDim.x) v |= ei32[i];
        if (v) atomicOr(&acc, 1);
        __syncthreads();
        if (tid == 0) g_is64 = (acc == 0) ? 1 : 0;
    } else if (b < 1 + zB) {
        int i = (b - 1) * 256 + tid;
        if (i < n) g_deg[i] = 0;
    } else if (b < 1 + zB + bW1) {
        int i = (b - 1 - zB) * 256 + tid;
        if (i < F0 * FH) {
            int k = i / FH, nidx = i % FH;
            __nv_bfloat16 hi, lo;
            split1(W1[i], hi, lo);
            g_W1thi[nidx * F0 + k] = hi;
            g_W1tlo[nidx * F0 + k] = lo;
        }
    } else if (b < 1 + zB + bW1 + bW2) {
        int i = (b - 1 - zB - bW1) * 256 + tid;
        if (i < FH * FH) {
            int k = i / FH, nidx = i % FH;
            __nv_bfloat16 hi, lo;
            split1(W2[i], hi, lo);
            g_W2thi[nidx * FH + k] = hi;
            g_W2tlo[nidx * FH + k] = lo;
        }
    } else {
        int i = (b - 1 - zB - bW1 - bW2) * 256 + tid;
        if (i < 64 * FH) {
            int nidx = i / FH, k = i % FH;
            float f = (nidx < FC) ? Wc[k * FC + nidx] : 0.f;
            __nv_bfloat16 hi, lo;
            split1(f, hi, lo);
            g_Wcthi[nidx * FH + k] = hi;
            g_Wctlo[nidx * FH + k] = lo;
        }
    }
}

// ============ scan: exclusive prefix of g_deg -> g_rowptr (1 block, 1024 thr)
__global__ void scan_kernel(int n) {
    __shared__ int sh[1024];
    int tid = threadIdx.x;
    int chunk = (n + 1023) >> 10;
    int start = tid * chunk, end = min(start + chunk, n);
    int sum = 0;
    for (int i = start; i < end; i++) sum += g_deg[i];
    sh[tid] = sum;
    __syncthreads();
    for (int off = 1; off < 1024; off <<= 1) {
        int v = 0;
        if (tid >= off) v = sh[tid - off];
        __syncthreads();
        sh[tid] += v;
        __syncthreads();
    }
    int run = sh[tid] - sum;
    for (int i = start; i < end; i++) { g_rowptr[i] = run; run += g_deg[i]; }
    if (end == n) g_rowptr[n] = run;
}

// ============ shared MMA compute for one 32-wide K chunk =====================
__device__ __forceinline__ void compute_chunk(
    uint32_t aAhi, uint32_t aAlo, uint32_t aBhi, uint32_t aBlo,
    int warp_m, int warp_n, int lane, float acc[2][8][4])
{
    #pragma unroll
    for (int kk = 0; kk < 32; kk += 16) {
        uint32_t ah[2][4], al[2][4];
        #pragma unroll
        for (int mi = 0; mi < 2; mi++) {
            int row = warp_m * 32 + mi * 16 + (lane & 15);
            int col = kk + (lane >> 4) * 8;
            uint32_t off = (uint32_t)(row * SKEW + col) * 2;
            LDSM_X4(ah[mi][0], ah[mi][1], ah[mi][2], ah[mi][3], aAhi + off);
            LDSM_X4(al[mi][0], al[mi][1], al[mi][2], al[mi][3], aAlo + off);
        }
        uint32_t b[8][2];
        int g = lane >> 3;
        #pragma unroll
        for (int p = 0; p < 4; p++) {
            int nrow = warp_n * 64 + p * 16 + (g >> 1) * 8 + (lane & 7);
            int col = kk + (g & 1) * 8;
            uint32_t off = (uint32_t)(nrow * SKEW + col) * 2;
            uint32_t r0, r1, r2, r3;
            LDSM_X4(r0, r1, r2, r3, aBhi + off);
            b[p * 2][0] = r0; b[p * 2][1] = r1;
            b[p * 2 + 1][0] = r2; b[p * 2 + 1][1] = r3;
        }
        #pragma unroll
        for (int mi = 0; mi < 2; mi++)
            #pragma unroll
            for (int ni = 0; ni < 8; ni++) {
                MMA16816(acc[mi][ni], ah[mi], b[ni]);
                MMA16816(acc[mi][ni], al[mi], b[ni]);
            }
        #pragma unroll
        for (int p = 0; p < 4; p++) {
            int nrow = warp_n * 64 + p * 16 + (g >> 1) * 8 + (lane & 7);
            int col = kk + (g & 1) * 8;
            uint32_t off = (uint32_t)(nrow * SKEW + col) * 2;
            uint32_t r0, r1, r2, r3;
            LDSM_X4(r0, r1, r2, r3, aBlo + off);
            b[p * 2][0] = r0; b[p * 2][1] = r1;
            b[p * 2 + 1][0] = r2; b[p * 2 + 1][1] = r3;
        }
        #pragma unroll
        for (int mi = 0; mi < 2; mi++)
            #pragma unroll
            for (int ni = 0; ni < 8; ni++)
                MMA16816(acc[mi][ni], ah[mi], b[ni]);
    }
}

__device__ __forceinline__ void gemm_epilogue(float acc[2][8][4], int m0,
                                              int warp_m, int warp_n, int lane, int M) {
    int gid = lane >> 2, tig = lane & 3;
    #pragma unroll
    for (int mi = 0; mi < 2; mi++) {
        #pragma unroll
        for (int ni = 0; ni < 8; ni++) {
            int col = warp_n * 64 + ni * 8 + tig * 2;
            int r0 = m0 + warp_m * 32 + mi * 16 + gid;
            if (r0 < M)
                *(float2*)(g_h + (size_t)r0 * 128 + col) =
                    make_float2(acc[mi][ni][0], acc[mi][ni][1]);
            int r1 = r0 + 8;
            if (r1 < M)
                *(float2*)(g_h + (size_t)r1 * 128 + col) =
                    make_float2(acc[mi][ni][2], acc[mi][ni][3]);
        }
    }
}

// ============ GEMM-1: reads x fp32 directly, splits on the fly ===============
__device__ void mma_gemm1_dev(char* smem, int bidx, const float* __restrict__ x, int M) {
    uint32_t sb = smem_u32(smem);
    int tid = threadIdx.x, wid = tid >> 5, lane = tid & 31;
    int m0 = bidx * 128;
    int warp_m = wid & 3, warp_n = wid >> 2;
    const int K = F0, nch = K >> 5;   // 8

    float acc[2][8][4] = {};
    float4 f[4];

    #define L1_LOADB(c) do { \
        uint32_t base = sb + 2 * TILE_B + ((c) & 1) * (2 * TILE_B); \
        _Pragma("unroll") \
        for (int it = 0; it < 2; it++) { \
            int id = it * 256 + tid; \
            int row = id >> 2, seg = id & 3; \
            uint32_t soff = (uint32_t)(row * SKEW + seg * 8) * 2; \
            CP_ASYNC16(base + soff,          g_W1thi + (size_t)row * K + ((c) << 5) + seg * 8, 16); \
            CP_ASYNC16(base + TILE_B + soff, g_W1tlo + (size_t)row * K + ((c) << 5) + seg * 8, 16); \
        } \
        CP_COMMIT; \
    } while (0)
    #define L1_LOADA(c) do { \
        _Pragma("unroll") \
        for (int it = 0; it < 4; it++) { \
            int id = it * 256 + tid; \
            int row = id >> 3, seg = id & 7; \
            int gr = m0 + row; \
            f[it] = (gr < M) ? *(const float4*)(x + (size_t)gr * K + ((c) << 5) + seg * 4) \
                             : make_float4(0.f, 0.f, 0.f, 0.f); \
        } \
    } while (0)

    L1_LOADB(0);
    L1_LOADA(0);

    for (int c = 0; c < nch; c++) {
        __syncthreads();   // all prior reads of A smem & B[(c+1)&1] complete
        if (c + 1 < nch) L1_LOADB(c + 1);
        #pragma unroll
        for (int it = 0; it < 4; it++) {
            int id = it * 256 + tid;
            int row = id >> 3, seg = id & 7;
            __nv_bfloat16 h0, h1, h2, h3, l0, l1, l2, l3;
            split1(f[it].x, h0, l0); split1(f[it].y, h1, l1);
            split1(f[it].z, h2, l2); split1(f[it].w, h3, l3);
            __nv_bfloat162 hp0; hp0.x = h0; hp0.y = h1;
            __nv_bfloat162 hp1; hp1.x = h2; hp1.y = h3;
            __nv_bfloat162 lp0; lp0.x = l0; lp0.y = l1;
            __nv_bfloat162 lp1; lp1.x = l2; lp1.y = l3;
            uint32_t soff = (uint32_t)(row * SKEW + seg * 4) * 2;
            *(uint2*)(smem + soff) = make_uint2(*(uint32_t*)&hp0, *(uint32_t*)&hp1);
            *(uint2*)(smem + TILE_B + soff) = make_uint2(*(uint32_t*)&lp0, *(uint32_t*)&lp1);
        }
        if (c + 1 < nch) { L1_LOADA(c + 1); CP_WAIT(1); }
        else             { CP_WAIT(0); }
        __syncthreads();

        uint32_t aBhi = sb + 2 * TILE_B + (c & 1) * (2 * TILE_B);
        compute_chunk(sb, sb + TILE_B, aBhi, aBhi + TILE_B, warp_m, warp_n, lane, acc);
    }
    gemm_epilogue(acc, m0, warp_m, warp_n, lane, M);
    #undef L1_LOADB
    #undef L1_LOADA
}

// ============ K2: GEMM-1 ∥ degree histogram (deg hidden under gemm) ==========
__global__ void __launch_bounds__(256, 2) k2_gemm1_deg(
    const float* __restrict__ x, const void* __restrict__ ei, int M, int E, int gemmB) {
    extern __shared__ char smem[];
    if (blockIdx.x < gemmB) {
        mma_gemm1_dev(smem, blockIdx.x, x, M);
    } else {
        int is64 = g_is64;
        int base = ((blockIdx.x - gemmB) * 256 + threadIdx.x) * 4;
        #pragma unroll
        for (int j = 0; j < 4; j++) {
            int i = base + j;
            if (i >= E) break;
            int d = load_edge(ei, (long long)E + i, is64);
            if ((unsigned)d < (unsigned)NN)
                g_slot[i] = atomicAdd(&g_deg[d], 1);
        }
    }
}

// ============ K3: scatter (col only) ∥ dinv ==================================
__global__ void k3_scatter_dinv(const void* __restrict__ ei, int E, int n, int scatB) {
    if (blockIdx.x < scatB) {
        int is64 = g_is64;
        int base = (blockIdx.x * 256 + threadIdx.x) * 8;
        #pragma unroll
        for (int j = 0; j < 8; j++) {
            int i = base + j;
            if (i >= E) break;
            int s = load_edge(ei, i, is64);
            int d = load_edge(ei, (long long)E + i, is64);
            if ((unsigned)s >= (unsigned)NN || (unsigned)d >= (unsigned)NN) continue;
            g_col[g_rowptr[d] + g_slot[i]] = s;
        }
    } else {
        int i = (blockIdx.x - scatB) * 256 + threadIdx.x;
        if (i < n) g_dinv[i] = rsqrtf((float)g_deg[i] + 1.0f);
    }
}

// ---------------- aggregation: warp per node, 4-way ILP, bf16 hi/lo out ------
// out = relu( di * Σ dinv[s]·h[s] + di²·h[node] + bias )
__global__ void agg_kernel(const float* __restrict__ bias, int n) {
    int warp = (blockIdx.x * blockDim.x + threadIdx.x) >> 5;
    if (warp >= n) return;
    int lane = threadIdx.x & 31;
    int beg = g_rowptr[warp], end = g_rowptr[warp + 1];
    const float4* hv = (const float4*)g_h;

    float4 a0 = make_float4(0.f, 0.f, 0.f, 0.f), a1 = a0, a2 = a0, a3 = a0;
    int e = beg;
    for (; e + 4 <= end; e += 4) {
        int s0 = g_col[e],     s1 = g_col[e + 1];
        int s2 = g_col[e + 2], s3 = g_col[e + 3];
        float w0 = g_dinv[s0], w1 = g_dinv[s1];
        float w2 = g_dinv[s2], w3 = g_dinv[s3];
        float4 v0 = hv[(size_t)s0 * 32 + lane];
        float4 v1 = hv[(size_t)s1 * 32 + lane];
        float4 v2 = hv[(size_t)s2 * 32 + lane];
        float4 v3 = hv[(size_t)s3 * 32 + lane];
        a0.x += w0 * v0.x; a0.y += w0 * v0.y; a0.z += w0 * v0.z; a0.w += w0 * v0.w;
        a1.x += w1 * v1.x; a1.y += w1 * v1.y; a1.z += w1 * v1.z; a1.w += w1 * v1.w;
        a2.x += w2 * v2.x; a2.y += w2 * v2.y; a2.z += w2 * v2.z; a2.w += w2 * v2.w;
        a3.x += w3 * v3.x; a3.y += w3 * v3.y; a3.z += w3 * v3.z; a3.w += w3 * v3.w;
    }
    for (; e < end; e++) {
        int s0 = g_col[e];
        float w0 = g_dinv[s0];
        float4 v0 = hv[(size_t)s0 * 32 + lane];
        a0.x += w0 * v0.x; a0.y += w0 * v0.y; a0.z += w0 * v0.z; a0.w += w0 * v0.w;
    }
    a0.x += a1.x + a2.x + a3.x;
    a0.y += a1.y + a2.y + a3.y;
    a0.z += a1.z + a2.z + a3.z;
    a0.w += a1.w + a2.w + a3.w;

    float di = g_dinv[warp], di2 = di * di;
    float4 hs = hv[(size_t)warp * 32 + lane];
    float4 bb = ((const float4*)bias)[lane];
    float4 r;
    r.x = fmaxf(di * a0.x + di2 * hs.x + bb.x, 0.f);
    r.y = fmaxf(di * a0.y + di2 * hs.y + bb.y, 0.f);
    r.z = fmaxf(di * a0.z + di2 * hs.z + bb.z, 0.f);
    r.w = fmaxf(di * a0.w + di2 * hs.w + bb.w, 0.f);

    __nv_bfloat16 h0, h1, h2, h3, l0, l1, l2, l3;
    split1(r.x, h0, l0); split1(r.y, h1, l1);
    split1(r.z, h2, l2); split1(r.w, h3, l3);
    __nv_bfloat162 hp0; hp0.x = h0; hp0.y = h1;
    __nv_bfloat162 hp1; hp1.x = h2; hp1.y = h3;
    __nv_bfloat162 lp0; lp0.x = l0; lp0.y = l1;
    __nv_bfloat162 lp1; lp1.x = l2; lp1.y = l3;
    size_t idx2 = (size_t)warp * 64 + lane * 2;
    ((__nv_bfloat162*)g_Ahi)[idx2] = hp0;
    ((__nv_bfloat162*)g_Ahi)[idx2 + 1] = hp1;
    ((__nv_bfloat162*)g_Alo)[idx2] = lp0;
    ((__nv_bfloat162*)g_Alo)[idx2 + 1] = lp1;
}

// ============ GEMM-2: bf16 A from g_Ahi/g_Alo (cp.async 2-stage) =============
__device__ __forceinline__ void gemm2_load_stage(uint32_t sbase, int m0, int kc, int M) {
    int tid = threadIdx.x;
    #pragma unroll
    for (int it = 0; it < 2; it++) {
        int id = it * 256 + tid;
        int row = id >> 2, seg = id & 3;
        uint32_t soff = (uint32_t)(row * SKEW + seg * 8) * 2;
        int gr = m0 + row;
        int ok = (gr < M) ? 16 : 0;
        size_t grc = (gr < M) ? (size_t)gr : 0;
        CP_ASYNC16(sbase + soff,              g_Ahi + grc * FH + kc + seg * 8, ok);
        CP_ASYNC16(sbase + TILE_B + soff,     g_Alo + grc * FH + kc + seg * 8, ok);
        CP_ASYNC16(sbase + 2 * TILE_B + soff, g_W2thi + (size_t)row * FH + kc + seg * 8, 16);
        CP_ASYNC16(sbase + 3 * TILE_B + soff, g_W2tlo + (size_t)row * FH + kc + seg * 8, 16);
    }
}

__global__ void __launch_bounds__(256, 2) mma_gemm2(int M) {
    extern __shared__ char smem[];
    uint32_t sb = smem_u32(smem);
    int tid = threadIdx.x, wid = tid >> 5, lane = tid & 31;
    int m0 = blockIdx.x * 128;
    int warp_m = wid & 3, warp_n = wid >> 2;

    float acc[2][8][4] = {};
    const int nch = FH >> 5;   // 4

    gemm2_load_stage(sb, m0, 0, M);
    CP_COMMIT;
    for (int c = 0; c < nch; c++) {
        if (c + 1 < nch) {
            gemm2_load_stage(sb + ((c + 1) & 1) * STAGE_B, m0, (c + 1) << 5, M);
            CP_COMMIT;
            CP_WAIT(1);
        } else {
            CP_WAIT(0);
        }
        __syncthreads();
        uint32_t stg = sb + (c & 1) * STAGE_B;
        compute_chunk(stg, stg + TILE_B, stg + 2 * TILE_B, stg + 3 * TILE_B,
                      warp_m, warp_n, lane, acc);
        __syncthreads();
    }
    gemm_epilogue(acc, m0, warp_m, warp_n, lane, M);
}

// ============ classifier: bf16 HMMA, BM=128 BN=64(40) K=128, 3-term ==========
#define CTILE_A (128 * SKEW * 2)
#define CTILE_Bc (64 * SKEW * 2)
#define CSTAGE (2 * CTILE_A + 2 * CTILE_Bc)
#define CSM_TOTAL (2 * CSTAGE)

__device__ __forceinline__ void clf_load_stage(uint32_t sbase, int m0, int kc, int M) {
    int tid = threadIdx.x;
    #pragma unroll
    for (int it = 0; it < 2; it++) {
        int id = it * 256 + tid;
        int row = id >> 2, seg = id & 3;
        uint32_t soff = (uint32_t)(row * SKEW + seg * 8) * 2;
        int gr = m0 + row;
        int ok = (gr < M) ? 16 : 0;
        size_t grc = (gr < M) ? (size_t)gr : 0;
        CP_ASYNC16(sbase + soff,           g_Ahi + grc * FH + kc + seg * 8, ok);
        CP_ASYNC16(sbase + CTILE_A + soff, g_Alo + grc * FH + kc + seg * 8, ok);
    }
    {
        int row = tid >> 2, seg = tid & 3;
        uint32_t soff = (uint32_t)(row * SKEW + seg * 8) * 2;
        CP_ASYNC16(sbase + 2 * CTILE_A + soff,            g_Wcthi + (size_t)row * FH + kc + seg * 8, 16);
        CP_ASYNC16(sbase + 2 * CTILE_A + CTILE_Bc + soff, g_Wctlo + (size_t)row * FH + kc + seg * 8, 16);
    }
}

__global__ void __launch_bounds__(256, 2) mma_clf(const float* __restrict__ bias,
                                                  float* __restrict__ out, int M) {
    extern __shared__ char smem[];
    uint32_t sb = smem_u32(smem);
    int tid = threadIdx.x, wid = tid >> 5, lane = tid & 31;
    int m0 = blockIdx.x * 128;
    int warp_m = wid & 3, warp_n = wid >> 2;

    float acc[2][4][4] = {};
    const int nch = FH >> 5;

    clf_load_stage(sb, m0, 0, M);
    CP_COMMIT;
    for (int c = 0; c < nch; c++) {
        if (c + 1 < nch) {
            clf_load_stage(sb + ((c + 1) & 1) * CSTAGE, m0, (c + 1) << 5, M);
            CP_COMMIT;
            CP_WAIT(1);
        } else {
            CP_WAIT(0);
        }
        __syncthreads();

        uint32_t stg = sb + (c & 1) * CSTAGE;
        uint32_t aAhi = stg, aAlo = stg + CTILE_A;
        uint32_t aBhi = stg + 2 * CTILE_A, aBlo = aBhi + CTILE_Bc;

        #pragma unroll
        for (int kk = 0; kk < 32; kk += 16) {
            uint32_t ah[2][4], al[2][4];
            #pragma unroll
            for (int mi = 0; mi < 2; mi++) {
                int row = warp_m * 32 + mi * 16 + (lane & 15);
                int col = kk + (lane >> 4) * 8;
                uint32_t off = (uint32_t)(row * SKEW + col) * 2;
                LDSM_X4(ah[mi][0], ah[mi][1], ah[mi][2], ah[mi][3], aAhi + off);
                LDSM_X4(al[mi][0], al[mi][1], al[mi][2], al[mi][3], aAlo + off);
            }
            uint32_t b[4][2];
            int g = lane >> 3;
            #pragma unroll
            for (int p = 0; p < 2; p++) {
                int nrow = warp_n * 32 + p * 16 + (g >> 1) * 8 + (lane & 7);
                int col = kk + (g & 1) * 8;
                uint32_t off = (uint32_t)(nrow * SKEW + col) * 2;
                uint32_t r0, r1, r2, r3;
                LDSM_X4(r0, r1, r2, r3, aBhi + off);
                b[p * 2][0] = r0; b[p * 2][1] = r1;
                b[p * 2 + 1][0] = r2; b[p * 2 + 1][1] = r3;
            }
            #pragma unroll
            for (int mi = 0; mi < 2; mi++)
                #pragma unroll
                for (int ni = 0; ni < 4; ni++) {
                    MMA16816(acc[mi][ni], ah[mi], b[ni]);
                    MMA16816(acc[mi][ni], al[mi], b[ni]);
                }
            #pragma unroll
            for (int p = 0; p < 2; p++) {
                int nrow = warp_n * 32 + p * 16 + (g >> 1) * 8 + (lane & 7);
                int col = kk + (g & 1) * 8;
                uint32_t off = (uint32_t)(nrow * SKEW + col) * 2;
                uint32_t r0, r1, r2, r3;
                LDSM_X4(r0, r1, r2, r3, aBlo + off);
                b[p * 2][0] = r0; b[p * 2][1] = r1;
                b[p * 2 + 1][0] = r2; b[p * 2 + 1][1] = r3;
            }
            #pragma unroll
            for (int mi = 0; mi < 2; mi++)
                #pragma unroll
                for (int ni = 0; ni < 4; ni++)
                    MMA16816(acc[mi][ni], ah[mi], b[ni]);
        }
        __syncthreads();
    }

    int gid = lane >> 2, tig = lane & 3;
    #pragma unroll
    for (int mi = 0; mi < 2; mi++) {
        #pragma unroll
        for (int ni = 0; ni < 4; ni++) {
            int col = warp_n * 32 + ni * 8 + tig * 2;
            if (col >= FC) continue;
            float b0 = bias[col], b1 = bias[col + 1];
            int r0 = m0 + warp_m * 32 + mi * 16 + gid;
            if (r0 < M)
                *(float2*)(out + (size_t)r0 * FC + col) =
                    make_float2(acc[mi][ni][0] + b0, acc[mi][ni][1] + b1);
            int r1 = r0 + 8;
            if (r1 < M)
                *(float2*)(out + (size_t)r1 * FC + col) =
                    make_float2(acc[mi][ni][2] + b0, acc[mi][ni][3] + b1);
        }
    }
}

// ---------------- launch ----------------
extern "C" void kernel_launch(void* const* d_in, const int* in_sizes, int n_in,
                              void* d_out, int out_size) {
    const float* x  = (const float*)d_in[0];
    const void*  ei = d_in[1];
    const float* W1 = (const float*)d_in[2];
    const float* b1 = (const float*)d_in[3];
    const float* W2 = (const float*)d_in[4];
    const float* b2 = (const float*)d_in[5];
    const float* Wc = (const float*)d_in[6];
    const float* bc = (const float*)d_in[7];
    float*       out = (float*)d_out;

    const int n = in_sizes[0] / F0;   // 100000
    const int E = in_sizes[1] / 2;    // 1600000

    cudaFuncSetAttribute(k2_gemm1_deg, cudaFuncAttributeMaxDynamicSharedMemorySize, GSM_TOTAL);
    cudaFuncSetAttribute(mma_gemm2, cudaFuncAttributeMaxDynamicSharedMemorySize, GSM_TOTAL);
    cudaFuncSetAttribute(mma_clf, cudaFuncAttributeMaxDynamicSharedMemorySize, CSM_TOTAL);

    int zB    = (n + 255) / 256;              // 391
    int bW1   = (F0 * FH + 255) / 256;        // 128
    int bW2   = (FH * FH + 255) / 256;        // 64
    int bWc   = (64 * FH + 255) / 256;        // 32
    int gemmB = (n + 127) / 128;              // 782
    int degB  = (E + 1023) / 1024;            // 1563
    int scatB = (E + 2047) / 2048;            // 782
    int dinvB = (n + 255) / 256;              // 391

    // K0: detect ∥ zero ∥ weight splits
    k0_prep<<<1 + zB + bW1 + bW2 + bWc, 256>>>((const int*)ei, 2 * E, n,
                                               W1, W2, Wc, zB, bW1, bW2);
    // K2: gemm1 ∥ degree histogram
    k2_gemm1_deg<<<gemmB + degB, 256, GSM_TOTAL>>>(x, ei, n, E, gemmB);
    // scan (tiny)
    scan_kernel<<<1, 1024>>>(n);
    // K3: scatter ∥ dinv
    k3_scatter_dinv<<<scatB + dinvB, 256>>>(ei, E, n, scatB);
    // agg1 -> bf16 hi/lo
    agg_kernel<<<(n + 7) / 8, 256>>>(b1, n);
    // gemm2
    mma_gemm2<<<gemmB, 256, GSM_TOTAL>>>(n);
    // agg2 -> bf16 hi/lo (reads g_h written by gemm2)
    agg_kernel<<<(n + 7) / 8, 256>>>(b2, n);
    // classifier
    mma_clf<<<gemmB, 256, CSM_TOTAL>>>(bc, out, n);
}